// round 3
// baseline (speedup 1.0000x reference)
#include <cuda_runtime.h>

#define NN   65536
#define EDG  524288
#define NB_G 256
#define NPG  256
#define FEAT 64
#define EMB  128
#define SLOPE 0.01f

__device__ float d_cur[NN*EMB];
__device__ float d_agg[NN*EMB];        // conv0 agg [N,64]; later head outputs [4][N][32]
__device__ int   d_row[NN+1];
__device__ int   d_cnt[NN];
__device__ int   d_cursor[NN];
__device__ int   d_csrc[EDG];
__device__ int   d_bsum[256];
__device__ int   d_boff[256];
__device__ float d_colsum[EMB];
__device__ float d_colsum2[EMB];
__device__ float d_score[NN*4];
__device__ float d_smv[NN*4];
__device__ unsigned char d_maskv[NN];
__device__ int   d_kcnt[4];
__device__ int   d_kept[4*NN];
__device__ float d_gm[NB_G*4];
__device__ float d_gs[NB_G*4];
__device__ float d_thr[NB_G*4];
__device__ float d_gate[NN*4];
__device__ float d_pooled[NB_G*4*EMB];
__device__ float d_logits[NB_G*4];

__device__ __forceinline__ float lrelu(float v){ return v > 0.f ? v : SLOPE*v; }
__device__ __forceinline__ float neginf(){ return __int_as_float(0xff800000); }

// ---------------- CSR build (by dst) ----------------
__global__ void k_zero_cnt(){
    int i = blockIdx.x*blockDim.x + threadIdx.x;
    if (i < NN) d_cnt[i] = 0;
}
__global__ void k_hist(const int* __restrict__ dst){
    int e = blockIdx.x*blockDim.x + threadIdx.x;
    if (e < EDG) atomicAdd(&d_cnt[dst[e]], 1);
}
__global__ void k_scan1(){
    __shared__ int s[256];
    int gid = blockIdx.x*256 + threadIdx.x;
    int v = d_cnt[gid];
    s[threadIdx.x] = v; __syncthreads();
    for (int off = 1; off < 256; off <<= 1){
        int t = (threadIdx.x >= off) ? s[threadIdx.x-off] : 0;
        __syncthreads();
        s[threadIdx.x] += t; __syncthreads();
    }
    d_row[gid] = s[threadIdx.x] - v;
    if (threadIdx.x == 255) d_bsum[blockIdx.x] = s[255];
}
__global__ void k_scan2(){
    __shared__ int s[256];
    int v = d_bsum[threadIdx.x];
    s[threadIdx.x] = v; __syncthreads();
    for (int off = 1; off < 256; off <<= 1){
        int t = (threadIdx.x >= off) ? s[threadIdx.x-off] : 0;
        __syncthreads();
        s[threadIdx.x] += t; __syncthreads();
    }
    d_boff[threadIdx.x] = s[threadIdx.x] - v;
}
__global__ void k_scan3(){
    int gid = blockIdx.x*256 + threadIdx.x;
    int r = d_row[gid] + d_boff[blockIdx.x];
    d_row[gid] = r;
    d_cursor[gid] = r;
    if (gid == NN-1) d_row[NN] = EDG;
}
__global__ void k_fill(const int* __restrict__ src, const int* __restrict__ dst){
    int e = blockIdx.x*blockDim.x + threadIdx.x;
    if (e < EDG){
        int d = dst[e];
        int p = atomicAdd(&d_cursor[d], 1);
        d_csrc[p] = src[e];
    }
}

// ---------------- conv0: segment-max aggregation (warp per node) ----------------
__global__ void k_agg0(const float* __restrict__ x){
    int wid  = (blockIdx.x*blockDim.x + threadIdx.x) >> 5;
    int lane = threadIdx.x & 31;
    if (wid >= NN) return;
    int beg = d_row[wid], end = d_row[wid+1];
    float m0 = neginf(), m1 = neginf();
    for (int base = beg; base < end; base += 32){
        int j = base + lane;
        int s = (j < end) ? d_csrc[j] : 0;
        int c = min(32, end - base);
        for (int t = 0; t < c; t++){
            int ss = __shfl_sync(0xffffffffu, s, t);
            m0 = fmaxf(m0, x[ss*FEAT + lane]);
            m1 = fmaxf(m1, x[ss*FEAT + 32 + lane]);
        }
    }
    if (m0 == neginf()) m0 = 0.f;
    if (m1 == neginf()) m1 = 0.f;
    d_agg[wid*FEAT + lane]      = m0;
    d_agg[wid*FEAT + 32 + lane] = m1;
}

__global__ void k_zero_stats(){
    int t = threadIdx.x;
    if (t < EMB){ d_colsum[t] = 0.f; d_colsum2[t] = 0.f; }
    if (t < 4) d_kcnt[t] = 0;
}

// ---------------- conv0 GEMM + lrelu + bn-stat accumulate ----------------
// block: 64 rows x 128 cols, 256 threads, 8x4 reg tile
__global__ void k_gemm0(const float* __restrict__ Wrel, const float* __restrict__ Wroot,
                        const float* __restrict__ bias, const float* __restrict__ x){
    extern __shared__ float smem[];
    float* Wt = smem;               // [128][129] transposed
    float* As = smem + 128*129;     // [64][128]
    int tid = threadIdx.x;
    for (int idx = tid; idx < 128*128; idx += 256){
        int c = idx >> 7, k = idx & 127;
        float v = (k < 64) ? Wrel[c*64 + k] : Wroot[c*64 + (k-64)];
        Wt[k*129 + c] = v;
    }
    int row0 = blockIdx.x * 64;
    for (int idx = tid; idx < 64*128; idx += 256){
        int r = idx >> 7, k = idx & 127;
        As[r*128 + k] = (k < 64) ? d_agg[(row0+r)*FEAT + k] : x[(row0+r)*FEAT + (k-64)];
    }
    __syncthreads();
    int tc = tid & 31, tr = tid >> 5;
    float acc[8][4];
    #pragma unroll
    for (int i = 0; i < 8; i++){
        #pragma unroll
        for (int j = 0; j < 4; j++) acc[i][j] = 0.f;
    }
    for (int k = 0; k < 128; k++){
        float w0 = Wt[k*129 + tc],      w1 = Wt[k*129 + 32 + tc];
        float w2 = Wt[k*129 + 64 + tc], w3 = Wt[k*129 + 96 + tc];
        #pragma unroll
        for (int rr = 0; rr < 8; rr++){
            float a = As[(tr*8+rr)*128 + k];
            acc[rr][0] += a*w0; acc[rr][1] += a*w1;
            acc[rr][2] += a*w2; acc[rr][3] += a*w3;
        }
    }
    float s1[4] = {0,0,0,0}, s2[4] = {0,0,0,0};
    #pragma unroll
    for (int rr = 0; rr < 8; rr++){
        int row = row0 + tr*8 + rr;
        #pragma unroll
        for (int j = 0; j < 4; j++){
            int c = j*32 + tc;
            float h = lrelu(acc[rr][j] + bias[c]);
            d_cur[row*EMB + c] = h;
            s1[j] += h; s2[j] += h*h;
        }
    }
    __syncthreads();
    #pragma unroll
    for (int j = 0; j < 4; j++){
        As[tr*128 + (j*32+tc)]        = s1[j];
        As[1024 + tr*128 + (j*32+tc)] = s2[j];
    }
    __syncthreads();
    if (tid < 128){
        float a1 = 0.f, a2 = 0.f;
        #pragma unroll
        for (int t = 0; t < 8; t++){ a1 += As[t*128 + tid]; a2 += As[1024 + t*128 + tid]; }
        atomicAdd(&d_colsum[tid],  a1);
        atomicAdd(&d_colsum2[tid], a2);
    }
}

__global__ void k_bn0(const float* __restrict__ g, const float* __restrict__ b){
    int idx = blockIdx.x*blockDim.x + threadIdx.x;
    int c = idx & 127;
    float mu  = d_colsum[c]  * (1.f/NN);
    float var = d_colsum2[c] * (1.f/NN) - mu*mu;
    float r   = rsqrtf(var + 1e-5f);
    d_cur[idx] = g[c]*(d_cur[idx]-mu)*r + b[c];
}

// ---------------- pool scores: 4 dots per node (warp per node) ----------------
__global__ void k_score(const float* __restrict__ w4){
    __shared__ float ws[512];
    int tid = threadIdx.x;
    ws[tid] = w4[tid]; ws[tid+256] = w4[tid+256];
    __syncthreads();
    int node = blockIdx.x*8 + (tid >> 5);
    int lane = tid & 31;
    float4 cv = *(const float4*)&d_cur[node*EMB + lane*4];
    #pragma unroll
    for (int h = 0; h < 4; h++){
        const float* wp = &ws[h*128 + lane*4];
        float p = cv.x*wp[0] + cv.y*wp[1] + cv.z*wp[2] + cv.w*wp[3];
        #pragma unroll
        for (int off = 16; off; off >>= 1) p += __shfl_xor_sync(0xffffffffu, p, off);
        if (lane == 0) d_score[node*4 + h] = p;
    }
}

// ---------------- per-graph softmax stats + threshold (block per graph) ----------------
__global__ void k_seg(float min_score){
    __shared__ float4 red[256];
    __shared__ float m4[4];
    int g = blockIdx.x, t = threadIdx.x;
    float4 z = *(const float4*)&d_score[(g*NPG + t)*4];
    red[t] = z; __syncthreads();
    for (int off = 128; off; off >>= 1){
        if (t < off){
            float4 a = red[t], b = red[t+off];
            red[t] = make_float4(fmaxf(a.x,b.x), fmaxf(a.y,b.y), fmaxf(a.z,b.z), fmaxf(a.w,b.w));
        }
        __syncthreads();
    }
    if (t == 0){ float4 mm = red[0]; m4[0]=mm.x; m4[1]=mm.y; m4[2]=mm.z; m4[3]=mm.w; }
    __syncthreads();
    float4 e = make_float4(expf(z.x-m4[0]), expf(z.y-m4[1]), expf(z.z-m4[2]), expf(z.w-m4[3]));
    red[t] = e; __syncthreads();
    for (int off = 128; off; off >>= 1){
        if (t < off){
            float4 a = red[t], b = red[t+off];
            red[t] = make_float4(a.x+b.x, a.y+b.y, a.z+b.z, a.w+b.w);
        }
        __syncthreads();
    }
    if (t < 4){
        float s = (t==0)?red[0].x : (t==1)?red[0].y : (t==2)?red[0].z : red[0].w;
        d_gm[g*4+t] = m4[t];
        d_gs[g*4+t] = s;
        float smax = 1.f/(s + 1e-16f);            // sm at argmax (e = exp(0) = 1)
        d_thr[g*4+t] = fminf(smax - 1e-7f, min_score);
    }
}

// ---------------- keep decision + kept lists ----------------
__global__ void k_keep(){
    int n = blockIdx.x*blockDim.x + threadIdx.x;
    int g = n >> 8;
    float4 z = *(const float4*)&d_score[n*4];
    float zz[4] = {z.x, z.y, z.z, z.w};
    float so[4];
    unsigned char mask = 0;
    #pragma unroll
    for (int h = 0; h < 4; h++){
        float e  = expf(zz[h] - d_gm[g*4+h]);
        float sv = e / (d_gs[g*4+h] + 1e-16f);
        so[h] = sv;
        if (sv > d_thr[g*4+h]){
            mask |= (unsigned char)(1 << h);
            int slot = atomicAdd(&d_kcnt[h], 1);
            d_kept[h*NN + slot] = n;
        }
    }
    *(float4*)&d_smv[n*4] = make_float4(so[0], so[1], so[2], so[3]);
    d_maskv[n] = mask;
}

// ---------------- per-head GraphConv(max) over kept nodes ----------------
__global__ void k_headconv(const float* __restrict__ Wrel, const float* __restrict__ Wroot,
                           const float* __restrict__ bias){
    int h = blockIdx.y;
    int nk = d_kcnt[h];
    int tid = threadIdx.x;   // 128
    __shared__ float ax[EMB], xs[EMB];
    unsigned char bit = (unsigned char)(1 << h);
    for (int slot = blockIdx.x; slot < nk; slot += gridDim.x){
        int i = d_kept[h*NN + slot];
        float m = neginf();
        int beg = d_row[i], end = d_row[i+1];
        for (int j = beg; j < end; j++){
            int s = d_csrc[j];
            if (d_maskv[s] & bit)
                m = fmaxf(m, d_cur[s*EMB + tid] * d_smv[s*4 + h]);
        }
        ax[tid] = (m == neginf()) ? 0.f : m;
        xs[tid] = d_cur[i*EMB + tid] * d_smv[i*4 + h];
        __syncthreads();
        if (tid < 32){
            const float* wr = Wrel  + (h*32 + tid)*EMB;
            const float* wt = Wroot + (h*32 + tid)*EMB;
            float acc = bias[h*32 + tid];
            #pragma unroll 8
            for (int k = 0; k < EMB; k++) acc += ax[k]*wr[k] + xs[k]*wt[k];
            float o = lrelu(acc);
            d_agg[(h*NN + slot)*32 + tid] = o;
            atomicAdd(&d_colsum[h*32 + tid],  o);
            atomicAdd(&d_colsum2[h*32 + tid], o*o);
        }
        __syncthreads();
    }
}

// dense: cur = 0.5*cur + 0.25*bn(0); kept corrected after (+0.25*g*r*o)
__global__ void k_updbase(const float* __restrict__ g, const float* __restrict__ b){
    int idx = blockIdx.x*blockDim.x + threadIdx.x;
    int c = idx & 127;
    float mu  = d_colsum[c]  * (1.f/NN);
    float var = d_colsum2[c] * (1.f/NN) - mu*mu;
    float r   = rsqrtf(var + 1e-5f);
    float valz = g[c]*(0.f - mu)*r + b[c];
    d_cur[idx] = 0.5f*d_cur[idx] + 0.25f*valz;
}
__global__ void k_updkept(const float* __restrict__ g){
    int h = blockIdx.y;
    int nk = d_kcnt[h];
    int oc = threadIdx.x;   // 32
    int c = h*32 + oc;
    float mu  = d_colsum[c]  * (1.f/NN);
    float var = d_colsum2[c] * (1.f/NN) - mu*mu;
    float r   = rsqrtf(var + 1e-5f);
    float gr  = g[c]*r;
    for (int slot = blockIdx.x; slot < nk; slot += gridDim.x){
        int i = d_kept[h*NN + slot];
        float o = d_agg[(h*NN + slot)*32 + oc];
        d_cur[i*EMB + c] += 0.25f * gr * o;
    }
}

// ---------------- classifier gate MLP over kept nodes ----------------
__global__ void k_gate(const float* __restrict__ gW1, const float* __restrict__ gb1,
                       const float* __restrict__ gW2, const float* __restrict__ gb2){
    int c = blockIdx.y;
    int nk = d_kcnt[c];
    int tid = threadIdx.x;   // 128
    __shared__ float xp[EMB];
    __shared__ float red[128];
    for (int slot = blockIdx.x; slot < nk; slot += gridDim.x){
        int i = d_kept[c*NN + slot];
        xp[tid] = d_cur[i*EMB + tid] * d_smv[i*4 + c];
        __syncthreads();
        const float* w = gW1 + (c*128 + tid)*128;
        float acc = gb1[c*128 + tid];
        #pragma unroll 8
        for (int k = 0; k < 128; k++) acc += xp[k]*w[k];
        red[tid] = lrelu(acc) * gW2[c*128 + tid];
        __syncthreads();
        for (int off = 64; off; off >>= 1){
            if (tid < off) red[tid] += red[tid+off];
            __syncthreads();
        }
        if (tid == 0) d_gate[i*4 + c] = red[0] + gb2[c];
        __syncthreads();
    }
}

// ---------------- masked attention softmax + weighted pool ----------------
__global__ void k_pool(){
    int g = blockIdx.x, c = blockIdx.y, t = threadIdx.x;   // 256 threads
    __shared__ float aw[256];
    __shared__ float red[256];
    __shared__ float mS, sS;
    int n = g*NPG + t;
    int kept = (d_maskv[n] >> c) & 1;
    float z = kept ? d_gate[n*4 + c] : neginf();
    red[t] = z; __syncthreads();
    for (int off = 128; off; off >>= 1){
        if (t < off) red[t] = fmaxf(red[t], red[t+off]);
        __syncthreads();
    }
    if (t == 0){ float m = red[0]; mS = (m == neginf()) ? 0.f : m; }
    __syncthreads();
    float e = kept ? expf(z - mS) : 0.f;
    red[t] = e; __syncthreads();
    for (int off = 128; off; off >>= 1){
        if (t < off) red[t] += red[t+off];
        __syncthreads();
    }
    if (t == 0) sS = red[0];
    __syncthreads();
    aw[t] = (e / (sS + 1e-16f)) * d_smv[n*4 + c];
    __syncthreads();
    if (t < 128){
        float acc = 0.f;
        for (int nn = 0; nn < 256; nn++){
            float w = aw[nn];
            if (w != 0.f) acc += w * d_cur[(g*NPG + nn)*EMB + t];
        }
        d_pooled[(g*4 + c)*EMB + t] = acc;
    }
}

// ---------------- final MLP per (graph, head) ----------------
__global__ void k_final(const float* __restrict__ fW1, const float* __restrict__ fb1,
                        const float* __restrict__ fW2, const float* __restrict__ fb2){
    int g = blockIdx.x, c = blockIdx.y, tid = threadIdx.x;   // 128
    __shared__ float p[128];
    __shared__ float red[128];
    p[tid] = d_pooled[(g*4 + c)*EMB + tid];
    __syncthreads();
    const float* w = fW1 + (c*128 + tid)*128;
    float acc = fb1[c*128 + tid];
    #pragma unroll 8
    for (int k = 0; k < 128; k++) acc += p[k]*w[k];
    red[tid] = lrelu(acc) * fW2[c*128 + tid];
    __syncthreads();
    for (int off = 64; off; off >>= 1){
        if (tid < off) red[tid] += red[tid+off];
        __syncthreads();
    }
    if (tid == 0) d_logits[g*4 + c] = red[0] + fb2[c];
}

__global__ void k_out(float* __restrict__ out){
    int g = blockIdx.x*blockDim.x + threadIdx.x;
    if (g < NB_G){
        float z0 = d_logits[g*4+0], z1 = d_logits[g*4+1];
        float z2 = d_logits[g*4+2], z3 = d_logits[g*4+3];
        float m = fmaxf(fmaxf(z0,z1), fmaxf(z2,z3));
        float s = expf(z0-m) + expf(z1-m) + expf(z2-m) + expf(z3-m);
        float l = logf(s);
        out[g*4+0] = z0 - m - l;
        out[g*4+1] = z1 - m - l;
        out[g*4+2] = z2 - m - l;
        out[g*4+3] = z3 - m - l;
    }
}

extern "C" void kernel_launch(void* const* d_in, const int* in_sizes, int n_in,
                              void* d_out, int out_size){
    (void)in_sizes; (void)n_in; (void)out_size;
    const float* x      = (const float*)d_in[0];
    const int*   ei     = (const int*)  d_in[1];
    const int*   src    = ei;
    const int*   dst    = ei + EDG;
    const float* Wrel0  = (const float*)d_in[3];
    const float* Wroot0 = (const float*)d_in[4];
    const float* b0     = (const float*)d_in[5];
    const float* bn0g   = (const float*)d_in[6];
    const float* bn0b   = (const float*)d_in[7];
    const float* bpw    = (const float*)d_in[8];
    const float* bWrel  = (const float*)d_in[9];
    const float* bWroot = (const float*)d_in[10];
    const float* bb     = (const float*)d_in[11];
    const float* bbng   = (const float*)d_in[12];
    const float* bbnb   = (const float*)d_in[13];
    const float* cpw    = (const float*)d_in[14];
    const float* gW1    = (const float*)d_in[15];
    const float* gb1    = (const float*)d_in[16];
    const float* gW2    = (const float*)d_in[17];
    const float* gb2    = (const float*)d_in[18];
    const float* fW1    = (const float*)d_in[19];
    const float* fb1    = (const float*)d_in[20];
    const float* fW2    = (const float*)d_in[21];
    const float* fb2    = (const float*)d_in[22];
    float* out = (float*)d_out;

    cudaFuncSetAttribute(k_gemm0, cudaFuncAttributeMaxDynamicSharedMemorySize, 98816);

    // CSR by dst
    k_zero_cnt<<<NN/256, 256>>>();
    k_hist<<<EDG/256, 256>>>(dst);
    k_scan1<<<256, 256>>>();
    k_scan2<<<1, 256>>>();
    k_scan3<<<256, 256>>>();
    k_fill<<<EDG/256, 256>>>(src, dst);

    // conv0 -> lrelu -> bn0
    k_agg0<<<NN/8, 256>>>(x);
    k_zero_stats<<<1, 256>>>();
    k_gemm0<<<NN/64, 256, 98816>>>(Wrel0, Wroot0, b0, x);
    k_bn0<<<NN*EMB/256, 256>>>(bn0g, bn0b);

    // two multi-head pooling blocks
    for (int bi = 0; bi < 2; bi++){
        k_zero_stats<<<1, 256>>>();
        k_score<<<NN/8, 256>>>(bpw + bi*4*EMB);
        k_seg<<<NB_G, 256>>>(0.7f);
        k_keep<<<NN/256, 256>>>();
        {
            dim3 grid(256, 4);
            k_headconv<<<grid, 128>>>(bWrel + bi*4*32*EMB, bWroot + bi*4*32*EMB, bb + bi*4*32);
        }
        k_updbase<<<NN*EMB/256, 256>>>(bbng + bi*EMB, bbnb + bi*EMB);
        {
            dim3 grid(256, 4);
            k_updkept<<<grid, 32>>>(bbng + bi*EMB);
        }
    }

    // classifier heads
    k_zero_stats<<<1, 256>>>();
    k_score<<<NN/8, 256>>>(cpw);
    k_seg<<<NB_G, 256>>>(0.8f);
    k_keep<<<NN/256, 256>>>();
    {
        dim3 grid(256, 4);
        k_gate<<<grid, 128>>>(gW1, gb1, gW2, gb2);
    }
    {
        dim3 grid(NB_G, 4);
        k_pool<<<grid, 256>>>();
        k_final<<<grid, 128>>>(fW1, fb1, fW2, fb2);
    }
    k_out<<<1, 256>>>(out);
}

// round 4
// speedup vs baseline: 1.0394x; 1.0394x over previous
#include <cuda_runtime.h>

#define NN   65536
#define EDG  524288
#define NPG  256
#define EMB  128
#define SLOPE 0.01f

__device__ float d_cur[NN*EMB];
__device__ float d_agg[NN*64];
__device__ float d_hout[4*NN*32];
__device__ int   d_row[NN+1];
__device__ int   d_cnt[NN];
__device__ int   d_cursor[NN];
__device__ int   d_csrc[EDG];
__device__ int   d_bsum[256];
__device__ float d_cs1[3*128];
__device__ float d_cs2[3*128];
__device__ int   d_kc[12];
__device__ int   d_keptA[3*4*NN];
__device__ float d_smvA[3*NN*4];
__device__ unsigned char d_maskA[3*NN];

__device__ __forceinline__ float lrelu(float v){ return v > 0.f ? v : SLOPE*v; }
__device__ __forceinline__ float neginf(){ return __int_as_float(0xff800000); }
__device__ __forceinline__ void ffma2(unsigned long long &d, unsigned long long a, unsigned long long b){
    asm("fma.rn.f32x2 %0, %1, %2, %0;" : "+l"(d) : "l"(a), "l"(b));
}

// ---------------- init: zero cnt + all stats/counters ----------------
__global__ void k_init(){
    int i = blockIdx.x*256 + threadIdx.x;
    d_cnt[i] = 0;
    if (blockIdx.x == 0){
        int t = threadIdx.x;
        if (t < 128){
            #pragma unroll
            for (int s = 0; s < 3; s++){ d_cs1[s*128+t] = 0.f; d_cs2[s*128+t] = 0.f; }
        }
        if (t < 12) d_kc[t] = 0;
    }
}
__global__ void k_hist(const int* __restrict__ dst){
    int e = blockIdx.x*256 + threadIdx.x;
    atomicAdd(&d_cnt[dst[e]], 1);
}
__global__ void k_scan1(){
    __shared__ int s[256];
    int gid = blockIdx.x*256 + threadIdx.x;
    int v = d_cnt[gid];
    s[threadIdx.x] = v; __syncthreads();
    for (int off = 1; off < 256; off <<= 1){
        int t = (threadIdx.x >= off) ? s[threadIdx.x-off] : 0;
        __syncthreads();
        s[threadIdx.x] += t; __syncthreads();
    }
    d_row[gid] = s[threadIdx.x] - v;
    if (threadIdx.x == 255) d_bsum[blockIdx.x] = s[255];
}
__global__ void k_scan3b(){
    __shared__ int s[256];
    __shared__ int boff;
    int t = threadIdx.x, bid = blockIdx.x;
    s[t] = d_bsum[t]; __syncthreads();
    for (int off = 1; off < 256; off <<= 1){
        int u = (t >= off) ? s[t-off] : 0;
        __syncthreads();
        s[t] += u; __syncthreads();
    }
    if (t == 0) boff = s[bid] - d_bsum[bid];
    __syncthreads();
    int gid = bid*256 + t;
    int r = d_row[gid] + boff;
    d_row[gid] = r;
    d_cursor[gid] = r;
    if (gid == NN-1) d_row[NN] = EDG;
}
__global__ void k_fill(const int* __restrict__ src, const int* __restrict__ dst){
    int e = blockIdx.x*256 + threadIdx.x;
    int d = dst[e];
    int p = atomicAdd(&d_cursor[d], 1);
    d_csrc[p] = src[e];
}

// ---------------- conv0 segment-max (warp per node, float2) ----------------
__global__ void k_agg0(const float* __restrict__ x){
    int wid  = (blockIdx.x*blockDim.x + threadIdx.x) >> 5;
    int lane = threadIdx.x & 31;
    int beg = d_row[wid], end = d_row[wid+1];
    float2 m = make_float2(neginf(), neginf());
    for (int base = beg; base < end; base += 32){
        int j = base + lane;
        int s = (j < end) ? d_csrc[j] : 0;
        int c = min(32, end - base);
        for (int t = 0; t < c; t++){
            int ss = __shfl_sync(0xffffffffu, s, t);
            float2 v = *(const float2*)(x + ss*64 + lane*2);
            m.x = fmaxf(m.x, v.x); m.y = fmaxf(m.y, v.y);
        }
    }
    if (m.x == neginf()) m.x = 0.f;
    if (m.y == neginf()) m.y = 0.f;
    *(float2*)(d_agg + wid*64 + lane*2) = m;
}

// ---------------- conv0 GEMM (128x128 tile, 8x8/thread, FFMA2) ----------------
#define GSMEM (2*128*132*4 + 256*4)
__global__ void __launch_bounds__(256,1) k_gemm0(const float* __restrict__ Wrel,
        const float* __restrict__ Wroot, const float* __restrict__ bias,
        const float* __restrict__ x){
    extern __shared__ float smp[];
    float* As  = smp;
    float* Ws  = smp + 128*132;
    float* sc1 = smp + 2*128*132;
    float* sc2 = sc1 + 128;
    int tid = threadIdx.x;
    int row0 = blockIdx.x*128;
    for (int idx = tid; idx < 128*128; idx += 256){
        int r = idx >> 7, c = idx & 127;
        As[r*132+c] = (c < 64) ? d_agg[(row0+r)*64 + c] : x[(row0+r)*64 + (c-64)];
        Ws[r*132+c] = (c < 64) ? Wrel[r*64 + c] : Wroot[r*64 + (c-64)];
    }
    if (tid < 128){ sc1[tid] = 0.f; sc2[tid] = 0.f; }
    __syncthreads();
    int tx = tid & 15, ty = tid >> 4;
    unsigned long long acc[8][8];
    #pragma unroll
    for (int r = 0; r < 8; r++)
        #pragma unroll
        for (int c = 0; c < 8; c++) acc[r][c] = 0ull;
    int ra = ty*4, rb = 64 + ty*4;
    for (int k = 0; k < 128; k += 4){
        ulonglong2 a[8];
        #pragma unroll
        for (int r = 0; r < 4; r++){
            a[r]   = *(const ulonglong2*)(As + (ra+r)*132 + k);
            a[r+4] = *(const ulonglong2*)(As + (rb+r)*132 + k);
        }
        #pragma unroll
        for (int cc = 0; cc < 8; cc++){
            ulonglong2 w = *(const ulonglong2*)(Ws + (cc*16+tx)*132 + k);
            #pragma unroll
            for (int r = 0; r < 8; r++){
                ffma2(acc[r][cc], a[r].x, w.x);
                ffma2(acc[r][cc], a[r].y, w.y);
            }
        }
    }
    #pragma unroll
    for (int cc = 0; cc < 8; cc++){
        int col = cc*16 + tx;
        float b = __ldg(&bias[col]);
        float a1 = 0.f, a2 = 0.f;
        #pragma unroll
        for (int r = 0; r < 8; r++){
            float2 f = *(float2*)&acc[r][cc];
            float h = f.x + f.y + b;
            h = (h > 0.f) ? h : SLOPE*h;
            int row = row0 + ((r < 4) ? (ra+r) : (rb+r-4));
            d_cur[row*EMB + col] = h;
            a1 += h; a2 += h*h;
        }
        atomicAdd(&sc1[col], a1);
        atomicAdd(&sc2[col], a2);
    }
    __syncthreads();
    if (tid < 128){
        atomicAdd(&d_cs1[tid], sc1[tid]);
        atomicAdd(&d_cs2[tid], sc2[tid]);
    }
}

// ---------------- fused stage: transform cur + scores + softmax + keep ----------------
// mode 0: cur = bn0(cur);  mode 1: cur = 0.5*cur + 0.25*bn(0) + kept? 0.25*g*r*o
__global__ void k_stage(int stage, const float* __restrict__ bng, const float* __restrict__ bnb,
                        const float* __restrict__ w4, float min_score, int mode){
    __shared__ float sscale[128], sshift[128], scorr[128], sw[512];
    __shared__ float4 red[256];
    __shared__ float sm4[4], ssum[4], sthr[4];
    int t = threadIdx.x;
    const float* cs1 = d_cs1 + stage*128;
    const float* cs2 = d_cs2 + stage*128;
    if (t < 128){
        float mu  = cs1[t] * (1.f/NN);
        float var = cs2[t] * (1.f/NN) - mu*mu;
        float r   = rsqrtf(var + 1e-5f);
        float gr  = bng[t]*r;
        if (mode == 0){ sscale[t] = gr;   sshift[t] = bnb[t] - gr*mu;          scorr[t] = 0.f; }
        else          { sscale[t] = 0.5f; sshift[t] = 0.25f*(bnb[t] - gr*mu);  scorr[t] = 0.25f*gr; }
    }
    sw[t] = w4[t]; sw[t+256] = w4[t+256];
    __syncthreads();
    int n = blockIdx.x*NPG + t;
    unsigned char pm = mode ? d_maskA[(stage-1)*NN + n] : 0;
    float* cur = d_cur + n*EMB;
    float s0 = 0.f, s1 = 0.f, s2 = 0.f, s3 = 0.f;
    for (int c4 = 0; c4 < 128; c4 += 4){
        float4 v  = *(float4*)(cur + c4);
        float4 scv = *(float4*)(sscale + c4);
        float4 shv = *(float4*)(sshift + c4);
        v.x = scv.x*v.x + shv.x; v.y = scv.y*v.y + shv.y;
        v.z = scv.z*v.z + shv.z; v.w = scv.w*v.w + shv.w;
        int hd = c4 >> 5;
        if (pm & (1u << hd)){
            float4 o  = *(const float4*)(d_hout + ((hd*NN + n)*32) + (c4 & 31));
            float4 cr = *(float4*)(scorr + c4);
            v.x += cr.x*o.x; v.y += cr.y*o.y; v.z += cr.z*o.z; v.w += cr.w*o.w;
        }
        *(float4*)(cur + c4) = v;
        s0 += v.x*sw[c4] + v.y*sw[c4+1] + v.z*sw[c4+2] + v.w*sw[c4+3];
        s1 += v.x*sw[128+c4] + v.y*sw[128+c4+1] + v.z*sw[128+c4+2] + v.w*sw[128+c4+3];
        s2 += v.x*sw[256+c4] + v.y*sw[256+c4+1] + v.z*sw[256+c4+2] + v.w*sw[256+c4+3];
        s3 += v.x*sw[384+c4] + v.y*sw[384+c4+1] + v.z*sw[384+c4+2] + v.w*sw[384+c4+3];
    }
    // block-wide max per head
    red[t] = make_float4(s0, s1, s2, s3); __syncthreads();
    for (int off = 128; off; off >>= 1){
        if (t < off){
            float4 a = red[t], b = red[t+off];
            red[t] = make_float4(fmaxf(a.x,b.x), fmaxf(a.y,b.y), fmaxf(a.z,b.z), fmaxf(a.w,b.w));
        }
        __syncthreads();
    }
    if (t == 0){ float4 mm = red[0]; sm4[0]=mm.x; sm4[1]=mm.y; sm4[2]=mm.z; sm4[3]=mm.w; }
    __syncthreads();
    float4 e = make_float4(expf(s0-sm4[0]), expf(s1-sm4[1]), expf(s2-sm4[2]), expf(s3-sm4[3]));
    red[t] = e; __syncthreads();
    for (int off = 128; off; off >>= 1){
        if (t < off){
            float4 a = red[t], b = red[t+off];
            red[t] = make_float4(a.x+b.x, a.y+b.y, a.z+b.z, a.w+b.w);
        }
        __syncthreads();
    }
    if (t == 0){ float4 ss = red[0]; ssum[0]=ss.x; ssum[1]=ss.y; ssum[2]=ss.z; ssum[3]=ss.w; }
    __syncthreads();
    if (t < 4) sthr[t] = fminf(1.f/(ssum[t] + 1e-16f) - 1e-7f, min_score);
    __syncthreads();
    float sv0 = e.x/(ssum[0]+1e-16f), sv1 = e.y/(ssum[1]+1e-16f);
    float sv2 = e.z/(ssum[2]+1e-16f), sv3 = e.w/(ssum[3]+1e-16f);
    int* kc = d_kc + stage*4;
    int* kept = d_keptA + stage*4*NN;
    unsigned char mk = 0;
    if (sv0 > sthr[0]){ mk |= 1; kept[0*NN + atomicAdd(kc+0,1)] = n; }
    if (sv1 > sthr[1]){ mk |= 2; kept[1*NN + atomicAdd(kc+1,1)] = n; }
    if (sv2 > sthr[2]){ mk |= 4; kept[2*NN + atomicAdd(kc+2,1)] = n; }
    if (sv3 > sthr[3]){ mk |= 8; kept[3*NN + atomicAdd(kc+3,1)] = n; }
    *(float4*)(d_smvA + (stage*NN + n)*4) = make_float4(sv0, sv1, sv2, sv3);
    d_maskA[stage*NN + n] = mk;
}

// ---------------- per-head GraphConv(max) over kept nodes ----------------
__global__ void k_headconv(int stage, const float* __restrict__ Wrel,
                           const float* __restrict__ Wroot, const float* __restrict__ bias){
    int h = blockIdx.y;
    int nk = d_kc[stage*4 + h];
    int tid = threadIdx.x;   // 128
    int oc = tid & 31, q = tid >> 5;
    __shared__ float ax[EMB], xs[EMB], red[128];
    const unsigned char* mv = d_maskA + stage*NN;
    const float* sv = d_smvA + stage*NN*4;
    const int* kept = d_keptA + stage*4*NN + h*NN;
    float* cs1 = d_cs1 + (stage+1)*128;
    float* cs2 = d_cs2 + (stage+1)*128;
    unsigned char bit = (unsigned char)(1 << h);
    for (int slot = blockIdx.x; slot < nk; slot += gridDim.x){
        int i = kept[slot];
        float m = neginf();
        int beg = d_row[i], end = d_row[i+1];
        for (int j = beg; j < end; j++){
            int s = d_csrc[j];
            if (mv[s] & bit)
                m = fmaxf(m, d_cur[s*EMB + tid] * sv[s*4 + h]);
        }
        ax[tid] = (m == neginf()) ? 0.f : m;
        xs[tid] = d_cur[i*EMB + tid] * sv[i*4 + h];
        __syncthreads();
        {
            const float* wr = Wrel  + (h*32 + oc)*EMB + q*32;
            const float* wt = Wroot + (h*32 + oc)*EMB + q*32;
            float acc = 0.f;
            #pragma unroll 8
            for (int k = 0; k < 32; k++) acc += ax[q*32+k]*wr[k] + xs[q*32+k]*wt[k];
            red[tid] = acc;
        }
        __syncthreads();
        if (q == 0){
            float o = red[oc] + red[32+oc] + red[64+oc] + red[96+oc] + bias[h*32+oc];
            o = lrelu(o);
            d_hout[(h*NN + i)*32 + oc] = o;
            atomicAdd(&cs1[h*32 + oc], o);
            atomicAdd(&cs2[h*32 + oc], o*o);
        }
        __syncthreads();
    }
}

// ---------------- classifier: gate + attention pool + final MLP + log_softmax ----------------
__global__ void k_cls(const float* __restrict__ gW1, const float* __restrict__ gb1,
                      const float* __restrict__ gW2, const float* __restrict__ gb2,
                      const float* __restrict__ fW1, const float* __restrict__ fb1,
                      const float* __restrict__ fW2, const float* __restrict__ fb2,
                      float* __restrict__ out){
    int g = blockIdx.x, t = threadIdx.x;   // 128 threads
    __shared__ float xp[128], pooled[128], red[128], gates[16], slog[4];
    __shared__ int knod[16], kn;
    const unsigned char* mv = d_maskA + 2*NN;
    const float* sv = d_smvA + 2*NN*4;
    for (int c = 0; c < 4; c++){
        if (t == 0) kn = 0;
        __syncthreads();
        for (int n0 = t; n0 < NPG; n0 += 128){
            int n = g*NPG + n0;
            if ((mv[n] >> c) & 1){
                int idx = atomicAdd(&kn, 1);
                if (idx < 16) knod[idx] = n;
            }
        }
        __syncthreads();
        int K = min(kn, 16);
        for (int ki = 0; ki < K; ki++){
            int i = knod[ki];
            xp[t] = d_cur[i*EMB + t] * sv[i*4 + c];
            __syncthreads();
            const float* w = gW1 + (c*128 + t)*128;
            float acc = gb1[c*128 + t];
            #pragma unroll 8
            for (int k = 0; k < 128; k++) acc += xp[k]*w[k];
            red[t] = lrelu(acc) * gW2[c*128 + t];
            __syncthreads();
            for (int off = 64; off; off >>= 1){
                if (t < off) red[t] += red[t+off];
                __syncthreads();
            }
            if (t == 0) gates[ki] = red[0] + gb2[c];
            __syncthreads();
        }
        // softmax over kept gates (all threads redundantly)
        float m = neginf();
        for (int ki = 0; ki < K; ki++) m = fmaxf(m, gates[ki]);
        float s = 0.f;
        for (int ki = 0; ki < K; ki++) s += expf(gates[ki] - m);
        float inv = 1.f/(s + 1e-16f);
        float p = 0.f;
        for (int ki = 0; ki < K; ki++){
            int i = knod[ki];
            float aw = expf(gates[ki] - m) * inv * sv[i*4 + c];
            p += aw * d_cur[i*EMB + t];
        }
        pooled[t] = p;
        __syncthreads();
        {
            const float* w = fW1 + (c*128 + t)*128;
            float acc = fb1[c*128 + t];
            #pragma unroll 8
            for (int k = 0; k < 128; k++) acc += pooled[k]*w[k];
            red[t] = lrelu(acc) * fW2[c*128 + t];
        }
        __syncthreads();
        for (int off = 64; off; off >>= 1){
            if (t < off) red[t] += red[t+off];
            __syncthreads();
        }
        if (t == 0) slog[c] = red[0] + fb2[c];
        __syncthreads();
    }
    if (t == 0){
        float z0 = slog[0], z1 = slog[1], z2 = slog[2], z3 = slog[3];
        float m = fmaxf(fmaxf(z0,z1), fmaxf(z2,z3));
        float l = logf(expf(z0-m) + expf(z1-m) + expf(z2-m) + expf(z3-m));
        out[g*4+0] = z0 - m - l;
        out[g*4+1] = z1 - m - l;
        out[g*4+2] = z2 - m - l;
        out[g*4+3] = z3 - m - l;
    }
}

extern "C" void kernel_launch(void* const* d_in, const int* in_sizes, int n_in,
                              void* d_out, int out_size){
    (void)in_sizes; (void)n_in; (void)out_size;
    const float* x      = (const float*)d_in[0];
    const int*   ei     = (const int*)  d_in[1];
    const int*   src    = ei;
    const int*   dst    = ei + EDG;
    const float* Wrel0  = (const float*)d_in[3];
    const float* Wroot0 = (const float*)d_in[4];
    const float* b0     = (const float*)d_in[5];
    const float* bn0g   = (const float*)d_in[6];
    const float* bn0b   = (const float*)d_in[7];
    const float* bpw    = (const float*)d_in[8];
    const float* bWrel  = (const float*)d_in[9];
    const float* bWroot = (const float*)d_in[10];
    const float* bb     = (const float*)d_in[11];
    const float* bbng   = (const float*)d_in[12];
    const float* bbnb   = (const float*)d_in[13];
    const float* cpw    = (const float*)d_in[14];
    const float* gW1    = (const float*)d_in[15];
    const float* gb1    = (const float*)d_in[16];
    const float* gW2    = (const float*)d_in[17];
    const float* gb2    = (const float*)d_in[18];
    const float* fW1    = (const float*)d_in[19];
    const float* fb1    = (const float*)d_in[20];
    const float* fW2    = (const float*)d_in[21];
    const float* fb2    = (const float*)d_in[22];
    float* out = (float*)d_out;

    cudaFuncSetAttribute(k_gemm0, cudaFuncAttributeMaxDynamicSharedMemorySize, GSMEM);

    k_init<<<NN/256, 256>>>();
    k_hist<<<EDG/256, 256>>>(dst);
    k_scan1<<<256, 256>>>();
    k_scan3b<<<256, 256>>>();
    k_fill<<<EDG/256, 256>>>(src, dst);
    k_agg0<<<NN/8, 256>>>(x);
    k_gemm0<<<NN/128, 256, GSMEM>>>(Wrel0, Wroot0, b0, x);

    // stage 0: bn0 + pool scores (block 0), then head convs
    k_stage<<<256, 256>>>(0, bn0g, bn0b, bpw + 0*512, 0.7f, 0);
    { dim3 gr(256,4); k_headconv<<<gr, 128>>>(0, bWrel + 0*4*32*EMB, bWroot + 0*4*32*EMB, bb + 0*128); }
    // stage 1: residual(block0 bn) + pool scores (block 1), then head convs
    k_stage<<<256, 256>>>(1, bbng + 0*EMB, bbnb + 0*EMB, bpw + 1*512, 0.7f, 1);
    { dim3 gr(256,4); k_headconv<<<gr, 128>>>(1, bWrel + 1*4*32*EMB, bWroot + 1*4*32*EMB, bb + 1*128); }
    // stage 2: residual(block1 bn) + classifier pool scores
    k_stage<<<256, 256>>>(2, bbng + 1*EMB, bbnb + 1*EMB, cpw, 0.8f, 1);

    k_cls<<<256, 128>>>(gW1, gb1, gW2, gb2, fW1, fb1, fW2, fb2, out);
}